// round 8
// baseline (speedup 1.0000x reference)
#include <cuda_runtime.h>
#include <cstdint>
#include <cstddef>

// Shapes: N=1, L=384, NODE=256, H=8, HD=32, PD=128, D1=1280
#define L 384
#define SPAT 147456       // 384*384
#define NODE 256
#define NH 8
#define HD 32
#define PD 128

// ---- scratch layout (floats) ----
#define OFF_Q       0          // 98304
#define OFF_K       98304
#define OFF_V       196608
#define OFF_A2H     294912     // 16*147456 = 2359296
#define OFF_A8      2654208    // 8*147456 = 1179648
#define OFF_AFIN    3833856    // 1179648
#define OFF_CAT     5013504    // 384*1280 = 491520
#define OFF_CATN    5505024    // 491520
#define OFF_H1      5996544    // 384*512
#define OFF_H2      6193152    // 384*512
#define OFF_H3      6389760    // 384*256
#define OFF_WT      6488064    // 136*9*128 = 156672
#define OFF_MEAN16  6644736
#define OFF_RSTD16  6644752
#define OFF_MEAN9   6644768
#define OFF_RSTD9   6644784
#define OFF_MEAN136 6644800    // 160 slots
#define OFF_RSTD136 6644960    // 160 slots
#define OFF_PSUM    6645120    // 128*384
#define OFF_PSQ     6694272    // 128*384
#define SCRATCH_FLOATS 6743424

__device__ float g_scratch[SCRATCH_FLOATS];

__device__ __forceinline__ float lrelu(float v){ return v >= 0.f ? v : 0.01f*v; }

// ------------------------------------------------------------------
// q,k,v = x @ Wq/Wk/Wv     grid 384, block 256
// ------------------------------------------------------------------
__global__ void qkv_kernel(const float* __restrict__ x, const float* __restrict__ Wq,
                           const float* __restrict__ Wk, const float* __restrict__ Wv,
                           float* __restrict__ q, float* __restrict__ k, float* __restrict__ v){
    __shared__ float xs[256];
    int l = blockIdx.x, t = threadIdx.x;
    xs[t] = x[l*256 + t];
    __syncthreads();
    float aq = 0.f, ak = 0.f, av = 0.f;
    #pragma unroll 4
    for (int i = 0; i < 256; i++){
        float xv = xs[i];
        aq += xv * Wq[i*256 + t];
        ak += xv * Wk[i*256 + t];
        av += xv * Wv[i*256 + t];
    }
    q[l*256 + t] = aq; k[l*256 + t] = ak; v[l*256 + t] = av;
}

// ------------------------------------------------------------------
// a_pair[h][l][m] = z[l,m,:] . Wp2a[:,h]   (channels 0..7 of a2h)
// grid (48, 384), block 256 (8 warps, warp per (l,m))
// ------------------------------------------------------------------
__global__ void apair_kernel(const float* __restrict__ z, const float* __restrict__ Wp2a,
                             float* __restrict__ a2h){
    __shared__ float ws[128*9]; // padded: ws[p*9+h]
    int t = threadIdx.x;
    for (int i = t; i < 1024; i += 256){
        int p = i >> 3, h = i & 7;
        ws[p*9 + h] = Wp2a[i];
    }
    __syncthreads();
    int lane = t & 31, wp = t >> 5;
    int m = blockIdx.x*8 + wp;
    int l = blockIdx.y;
    const float4 zv = *(const float4*)(z + ((size_t)l*L + m)*128 + lane*4);
    int p = lane*4;
    float acc[8];
    #pragma unroll
    for (int h = 0; h < 8; h++){
        acc[h] = zv.x*ws[p*9 + h] + zv.y*ws[(p+1)*9 + h]
               + zv.z*ws[(p+2)*9 + h] + zv.w*ws[(p+3)*9 + h];
    }
    #pragma unroll
    for (int h = 0; h < 8; h++){
        float s = acc[h];
        for (int o = 16; o > 0; o >>= 1) s += __shfl_down_sync(0xffffffffu, s, o);
        if (lane == 0) a2h[h*SPAT + l*L + m] = s;
    }
}

// ------------------------------------------------------------------
// a_node[h][l][m] = q[l,h,:].k[m,h,:]/sqrt(32)  (channels 8..15)
// grid (12,12,8), block (32,32)
// ------------------------------------------------------------------
__global__ void anode_kernel(const float* __restrict__ q, const float* __restrict__ k,
                             float* __restrict__ a2h){
    int h = blockIdx.z;
    int l0 = blockIdx.y*32, m0 = blockIdx.x*32;
    __shared__ float Qs[32][33], Ks[32][33];
    int tx = threadIdx.x, ty = threadIdx.y;
    Qs[ty][tx] = q[(l0+ty)*256 + h*32 + tx];
    Ks[ty][tx] = k[(m0+ty)*256 + h*32 + tx];
    __syncthreads();
    float acc = 0.f;
    #pragma unroll
    for (int d = 0; d < 32; d++) acc += Qs[ty][d]*Ks[tx][d];
    a2h[(8+h)*SPAT + (l0+ty)*L + m0 + tx] = acc * 0.17677669529663687f;
}

// ------------------------------------------------------------------
// Per-channel instance-norm stats for channel-first contiguous buffers
// grid = #channels, block 256.  channel c<nA from srcA, else srcB.
// ------------------------------------------------------------------
__global__ void stats_kernel(const float* __restrict__ srcA, int nA,
                             const float* __restrict__ srcB,
                             float* __restrict__ mean, float* __restrict__ rstd){
    int c = blockIdx.x, t = threadIdx.x;
    const float* p = (c < nA) ? srcA + (size_t)c*SPAT : srcB + (size_t)(c-nA)*SPAT;
    const float4* p4 = (const float4*)p;
    float s = 0.f, s2 = 0.f;
    for (int i = t; i < SPAT/4; i += 256){
        float4 v = p4[i];
        s  += v.x + v.y + v.z + v.w;
        s2 += v.x*v.x + v.y*v.y + v.z*v.z + v.w*v.w;
    }
    __shared__ float ss[256], ss2[256];
    ss[t] = s; ss2[t] = s2; __syncthreads();
    for (int o = 128; o > 0; o >>= 1){
        if (t < o){ ss[t] += ss[t+o]; ss2[t] += ss2[t+o]; }
        __syncthreads();
    }
    if (t == 0){
        float m = ss[0] * (1.f/SPAT);
        float var = ss2[0] * (1.f/SPAT) - m*m;
        mean[c] = m; rstd[c] = rsqrtf(var + 1e-5f);
    }
}

// z channel stats, stage 1: per-(l) partials, deterministic. grid 384, block 256.
__global__ void zstats1_kernel(const float* __restrict__ z,
                               float* __restrict__ psum, float* __restrict__ psq){
    int l = blockIdx.x, t = threadIdx.x;
    int c = t & 127, half = t >> 7;
    const float* base = z + (size_t)l*L*128;
    float s = 0.f, s2 = 0.f;
    for (int m = half; m < L; m += 2){
        float v = base[m*128 + c];
        s += v; s2 += v*v;
    }
    __shared__ float sh[256], sh2[256];
    sh[t] = s; sh2[t] = s2; __syncthreads();
    if (half == 0){
        psum[c*L + l] = sh[t] + sh[t+128];
        psq [c*L + l] = sh2[t] + sh2[t+128];
    }
}

// stage 2: reduce over l. grid 128, block 128.
__global__ void zstats2_kernel(const float* __restrict__ psum, const float* __restrict__ psq,
                               float* __restrict__ mean, float* __restrict__ rstd){
    int c = blockIdx.x, t = threadIdx.x;
    float s = 0.f, s2 = 0.f;
    for (int l = t; l < L; l += 128){ s += psum[c*L + l]; s2 += psq[c*L + l]; }
    __shared__ float ss[128], ss2[128];
    ss[t] = s; ss2[t] = s2; __syncthreads();
    for (int o = 64; o > 0; o >>= 1){
        if (t < o){ ss[t] += ss[t+o]; ss2[t] += ss2[t+o]; }
        __syncthreads();
    }
    if (t == 0){
        float m = ss[0] * (1.f/SPAT);
        float var = ss2[0] * (1.f/SPAT) - m*m;
        mean[c] = m; rstd[c] = rsqrtf(var + 1e-5f);
    }
}

// ------------------------------------------------------------------
// conv_a: 16ch (instance-normed a2h) -> 8ch, 3x3 SAME, leaky. grid (24,24), 256 thr
// ------------------------------------------------------------------
__global__ void conva_kernel(const float* __restrict__ a2h, const float* __restrict__ w,
                             const float* __restrict__ bias, const float* __restrict__ mean,
                             const float* __restrict__ rstd, float* __restrict__ a8){
    __shared__ float tin[16*324];
    __shared__ float wk[1152];
    int t = threadIdx.x;
    for (int i = t; i < 1152; i += 256) wk[i] = w[i];
    int x0 = blockIdx.x*16 - 1, y0 = blockIdx.y*16 - 1;
    for (int i = t; i < 16*324; i += 256){
        int c = i / 324, r = i % 324;
        int gy = y0 + r/18, gx = x0 + r%18;
        float v = 0.f;
        if ((unsigned)gy < 384u && (unsigned)gx < 384u)
            v = (a2h[c*SPAT + gy*L + gx] - mean[c]) * rstd[c];
        tin[i] = v;
    }
    __syncthreads();
    int lx = t & 15, ly = t >> 4;
    float acc[8];
    #pragma unroll
    for (int o = 0; o < 8; o++) acc[o] = bias[o];
    for (int c = 0; c < 16; c++){
        float iv[9];
        #pragma unroll
        for (int ky = 0; ky < 3; ky++)
            #pragma unroll
            for (int kx = 0; kx < 3; kx++)
                iv[ky*3+kx] = tin[c*324 + (ly+ky)*18 + lx + kx];
        #pragma unroll
        for (int o = 0; o < 8; o++){
            const float* wp = &wk[(o*16 + c)*9];
            acc[o] += wp[0]*iv[0]+wp[1]*iv[1]+wp[2]*iv[2]
                    + wp[3]*iv[3]+wp[4]*iv[4]+wp[5]*iv[5]
                    + wp[6]*iv[6]+wp[7]*iv[7]+wp[8]*iv[8];
        }
    }
    int gx = blockIdx.x*16 + lx, gy = blockIdx.y*16 + ly;
    #pragma unroll
    for (int o = 0; o < 8; o++)
        a8[o*SPAT + gy*L + gx] = lrelu(acc[o]);
}

// conv_m: 9ch (a8 normed + plddt normed) -> 8ch, leaky. grid (24,24), 256 thr
__global__ void convm_kernel(const float* __restrict__ a8, const float* __restrict__ plddt,
                             const float* __restrict__ w, const float* __restrict__ bias,
                             const float* __restrict__ mean, const float* __restrict__ rstd,
                             float* __restrict__ afin){
    __shared__ float tin[9*324];
    __shared__ float wk[648];
    int t = threadIdx.x;
    for (int i = t; i < 648; i += 256) wk[i] = w[i];
    int x0 = blockIdx.x*16 - 1, y0 = blockIdx.y*16 - 1;
    for (int i = t; i < 9*324; i += 256){
        int c = i / 324, r = i % 324;
        int gy = y0 + r/18, gx = x0 + r%18;
        float v = 0.f;
        if ((unsigned)gy < 384u && (unsigned)gx < 384u){
            float raw = (c < 8) ? a8[c*SPAT + gy*L + gx] : plddt[gy*L + gx];
            v = (raw - mean[c]) * rstd[c];
        }
        tin[i] = v;
    }
    __syncthreads();
    int lx = t & 15, ly = t >> 4;
    float acc[8];
    #pragma unroll
    for (int o = 0; o < 8; o++) acc[o] = bias[o];
    for (int c = 0; c < 9; c++){
        float iv[9];
        #pragma unroll
        for (int ky = 0; ky < 3; ky++)
            #pragma unroll
            for (int kx = 0; kx < 3; kx++)
                iv[ky*3+kx] = tin[c*324 + (ly+ky)*18 + lx + kx];
        #pragma unroll
        for (int o = 0; o < 8; o++){
            const float* wp = &wk[(o*9 + c)*9];
            acc[o] += wp[0]*iv[0]+wp[1]*iv[1]+wp[2]*iv[2]
                    + wp[3]*iv[3]+wp[4]*iv[4]+wp[5]*iv[5]
                    + wp[6]*iv[6]+wp[7]*iv[7]+wp[8]*iv[8];
        }
    }
    int gx = blockIdx.x*16 + lx, gy = blockIdx.y*16 + ly;
    #pragma unroll
    for (int o = 0; o < 8; o++)
        afin[o*SPAT + gy*L + gx] = lrelu(acc[o]);
}

// ------------------------------------------------------------------
// nfn: cat[l, 1024 + h*32+d] = sum_m afin[h][l][m] * v[m, h*32+d]
// grid (8 heads, 12 ltiles), block (32,32)
// ------------------------------------------------------------------
__global__ void nfn_kernel(const float* __restrict__ afin, const float* __restrict__ v,
                           float* __restrict__ cat){
    int h = blockIdx.x, l0 = blockIdx.y*32;
    int tx = threadIdx.x, ty = threadIdx.y;
    __shared__ float As[32][33], Vs[32][33];
    float acc = 0.f;
    for (int m0 = 0; m0 < L; m0 += 32){
        As[ty][tx] = afin[h*SPAT + (l0+ty)*L + m0 + tx];
        Vs[ty][tx] = v[(m0+ty)*256 + h*32 + tx];
        __syncthreads();
        #pragma unroll
        for (int kk = 0; kk < 32; kk++) acc += As[ty][kk]*Vs[kk][tx];
        __syncthreads();
    }
    cat[(size_t)(l0+ty)*1280 + 1024 + h*32 + tx] = acc;
}

// nfp: cat[l, h*128+p] = sum_m afin[h][l][m] * z[l,m,p].  grid 384, block 256
__global__ void nfp_kernel(const float* __restrict__ afin, const float* __restrict__ z,
                           float* __restrict__ cat){
    int l = blockIdx.x, t = threadIdx.x;
    __shared__ float As[8][32];
    __shared__ float Zs[32*128];
    int p = t & 127, hb = (t >> 7)*4;
    float acc0 = 0.f, acc1 = 0.f, acc2 = 0.f, acc3 = 0.f;
    for (int m0 = 0; m0 < L; m0 += 32){
        __syncthreads();
        { int hh = t >> 5, mm = t & 31; As[hh][mm] = afin[hh*SPAT + l*L + m0 + mm]; }
        const float4* zsrc = (const float4*)(z + ((size_t)l*L + m0)*128);
        float4* zd = (float4*)Zs;
        for (int i = t; i < 1024; i += 256) zd[i] = zsrc[i];
        __syncthreads();
        #pragma unroll 8
        for (int mm = 0; mm < 32; mm++){
            float zv = Zs[mm*128 + p];
            acc0 += As[hb  ][mm]*zv;
            acc1 += As[hb+1][mm]*zv;
            acc2 += As[hb+2][mm]*zv;
            acc3 += As[hb+3][mm]*zv;
        }
    }
    cat[(size_t)l*1280 + (hb  )*128 + p] = acc0;
    cat[(size_t)l*1280 + (hb+1)*128 + p] = acc1;
    cat[(size_t)l*1280 + (hb+2)*128 + p] = acc2;
    cat[(size_t)l*1280 + (hb+3)*128 + p] = acc3;
}

// ------------------------------------------------------------------
// row LayerNorm: out = [(in+add?) - m]/sqrt(v+eps)*w + b  (opt leaky)
// grid = rows, block 256, dyn smem D floats
// ------------------------------------------------------------------
__global__ void ln_kernel(const float* __restrict__ in, const float* __restrict__ add,
                          float* __restrict__ out, const float* __restrict__ w,
                          const float* __restrict__ b, int D, int do_leaky){
    extern __shared__ float sh[];
    __shared__ float red[256];
    int r = blockIdx.x, t = threadIdx.x;
    float s = 0.f;
    for (int i = t; i < D; i += 256){
        float v = in[(size_t)r*D + i];
        if (add) v += add[(size_t)r*D + i];
        sh[i] = v; s += v;
    }
    red[t] = s; __syncthreads();
    for (int o = 128; o > 0; o >>= 1){ if (t < o) red[t] += red[t+o]; __syncthreads(); }
    float mean = red[0] / D;
    __syncthreads();
    float s2 = 0.f;
    for (int i = t; i < D; i += 256){ float d = sh[i] - mean; s2 += d*d; }
    red[t] = s2; __syncthreads();
    for (int o = 128; o > 0; o >>= 1){ if (t < o) red[t] += red[t+o]; __syncthreads(); }
    float rstd = rsqrtf(red[0]/D + 1e-5f);
    for (int i = t; i < D; i += 256){
        float v = (sh[i] - mean)*rstd*w[i] + b[i];
        if (do_leaky) v = lrelu(v);
        out[(size_t)r*D + i] = v;
    }
}

// generic GEMM C = A(MxK) @ B(KxN) + bias.  block (16,16), tiles 32x32x32
__global__ void gemm_kernel(const float* __restrict__ A, const float* __restrict__ B,
                            const float* __restrict__ bias, float* __restrict__ C,
                            int M, int N, int K){
    __shared__ float As[32][33], Bs[32][33];
    int tx = threadIdx.x, ty = threadIdx.y;
    int t = ty*16 + tx;
    int r0 = blockIdx.y*32, c0 = blockIdx.x*32;
    float a00 = 0.f, a01 = 0.f, a10 = 0.f, a11 = 0.f;
    for (int k0 = 0; k0 < K; k0 += 32){
        for (int i = t; i < 1024; i += 256){
            int rr = i >> 5, cc = i & 31;
            As[rr][cc] = A[(size_t)(r0+rr)*K + k0 + cc];
            Bs[rr][cc] = B[(size_t)(k0+rr)*N + c0 + cc];
        }
        __syncthreads();
        #pragma unroll
        for (int kk = 0; kk < 32; kk++){
            float av0 = As[ty*2][kk], av1 = As[ty*2+1][kk];
            float bv0 = Bs[kk][tx*2], bv1 = Bs[kk][tx*2+1];
            a00 += av0*bv0; a01 += av0*bv1; a10 += av1*bv0; a11 += av1*bv1;
        }
        __syncthreads();
    }
    int r = r0 + ty*2, c = c0 + tx*2;
    C[(size_t)r*N + c]       = a00 + bias[c];
    C[(size_t)r*N + c+1]     = a01 + bias[c+1];
    C[(size_t)(r+1)*N + c]   = a10 + bias[c];
    C[(size_t)(r+1)*N + c+1] = a11 + bias[c+1];
}

// transpose conv_p weights (128,136,3,3) -> wt[(ci*9+k)*128 + po]
__global__ void wprep_kernel(const float* __restrict__ w, float* __restrict__ wt){
    int i = blockIdx.x*256 + threadIdx.x;  // 156672 total
    if (i < 156672){
        int po = i / 1224, rem = i % 1224;
        int ci = rem / 9, kk = rem % 9;
        wt[(ci*9 + kk)*128 + po] = w[i];
    }
}

// ------------------------------------------------------------------
// conv_p: 136ch (z + afin, instance-normed on the fly) -> 128ch, leaky,
// write channel-last (l,m,p). grid (12,12,8 ocg), block 256.
// Each thread: 4 horizontally adjacent pixels x 16 out channels.
// ------------------------------------------------------------------
__global__ void convp_kernel(const float* __restrict__ z, const float* __restrict__ afin,
                             const float* __restrict__ wt, const float* __restrict__ bias,
                             const float* __restrict__ mean136, const float* __restrict__ rstd136,
                             float* __restrict__ out){
    __shared__ float tin[4*1156];   // 4 channels x 34x34 halo
    __shared__ float wsm[576];      // 4ci x 9k x 16po
    int t = threadIdx.x;
    int x0b = blockIdx.x*32, y0 = blockIdx.y*32, ocg = blockIdx.z;
    int X0 = (t & 7)*4, y = t >> 3;

    float4 b0 = *(const float4*)(bias + ocg*16);
    float4 b1 = *(const float4*)(bias + ocg*16 + 4);
    float4 b2 = *(const float4*)(bias + ocg*16 + 8);
    float4 b3 = *(const float4*)(bias + ocg*16 + 12);
    float acc[4][16];
    #pragma unroll
    for (int px = 0; px < 4; px++){
        acc[px][0]=b0.x; acc[px][1]=b0.y; acc[px][2]=b0.z; acc[px][3]=b0.w;
        acc[px][4]=b1.x; acc[px][5]=b1.y; acc[px][6]=b1.z; acc[px][7]=b1.w;
        acc[px][8]=b2.x; acc[px][9]=b2.y; acc[px][10]=b2.z; acc[px][11]=b2.w;
        acc[px][12]=b3.x; acc[px][13]=b3.y; acc[px][14]=b3.z; acc[px][15]=b3.w;
    }

    for (int ci0 = 0; ci0 < 136; ci0 += 4){
        __syncthreads();
        // weights for this (ci chunk, ocg)
        for (int i = t; i < 576; i += 256){
            int c = i / 144, rr = i % 144, kk = rr >> 4, po = rr & 15;
            wsm[i] = wt[((ci0 + c)*9 + kk)*128 + ocg*16 + po];
        }
        float mm0 = mean136[ci0],   rr0 = rstd136[ci0];
        float mm1 = mean136[ci0+1], rr1 = rstd136[ci0+1];
        float mm2 = mean136[ci0+2], rr2 = rstd136[ci0+2];
        float mm3 = mean136[ci0+3], rr3 = rstd136[ci0+3];
        if (ci0 < 128){
            for (int i = t; i < 1156; i += 256){
                int hy = i / 34, hx = i - hy*34;
                int gy = y0 - 1 + hy, gx = x0b - 1 + hx;
                bool inb = ((unsigned)gy < 384u) && ((unsigned)gx < 384u);
                float4 v = make_float4(0.f,0.f,0.f,0.f);
                if (inb) v = *(const float4*)(z + (size_t)(gy*L + gx)*128 + ci0);
                tin[i]        = inb ? (v.x - mm0)*rr0 : 0.f;
                tin[1156 + i] = inb ? (v.y - mm1)*rr1 : 0.f;
                tin[2312 + i] = inb ? (v.z - mm2)*rr2 : 0.f;
                tin[3468 + i] = inb ? (v.w - mm3)*rr3 : 0.f;
            }
        } else {
            for (int i = t; i < 1156; i += 256){
                int hy = i / 34, hx = i - hy*34;
                int gy = y0 - 1 + hy, gx = x0b - 1 + hx;
                bool inb = ((unsigned)gy < 384u) && ((unsigned)gx < 384u);
                int sp = gy*L + gx;
                tin[i]        = inb ? (afin[(ci0-128)*SPAT + sp] - mm0)*rr0 : 0.f;
                tin[1156 + i] = inb ? (afin[(ci0-127)*SPAT + sp] - mm1)*rr1 : 0.f;
                tin[2312 + i] = inb ? (afin[(ci0-126)*SPAT + sp] - mm2)*rr2 : 0.f;
                tin[3468 + i] = inb ? (afin[(ci0-125)*SPAT + sp] - mm3)*rr3 : 0.f;
            }
        }
        __syncthreads();

        #pragma unroll
        for (int c = 0; c < 4; c++){
            float iv[3][6];
            #pragma unroll
            for (int ky = 0; ky < 3; ky++)
                #pragma unroll
                for (int j = 0; j < 6; j++)
                    iv[ky][j] = tin[c*1156 + (y+ky)*34 + X0 + j];
            #pragma unroll
            for (int ky = 0; ky < 3; ky++)
            #pragma unroll
            for (int kx = 0; kx < 3; kx++){
                const float* wp = &wsm[(c*9 + ky*3 + kx)*16];
                float4 w0 = *(const float4*)wp;
                float4 w1 = *(const float4*)(wp + 4);
                float4 w2 = *(const float4*)(wp + 8);
                float4 w3 = *(const float4*)(wp + 12);
                #pragma unroll
                for (int px = 0; px < 4; px++){
                    float inv = iv[ky][px + kx];
                    acc[px][0]  += inv*w0.x; acc[px][1]  += inv*w0.y;
                    acc[px][2]  += inv*w0.z; acc[px][3]  += inv*w0.w;
                    acc[px][4]  += inv*w1.x; acc[px][5]  += inv*w1.y;
                    acc[px][6]  += inv*w1.z; acc[px][7]  += inv*w1.w;
                    acc[px][8]  += inv*w2.x; acc[px][9]  += inv*w2.y;
                    acc[px][10] += inv*w2.z; acc[px][11] += inv*w2.w;
                    acc[px][12] += inv*w3.x; acc[px][13] += inv*w3.y;
                    acc[px][14] += inv*w3.z; acc[px][15] += inv*w3.w;
                }
            }
        }
    }
    int gy = y0 + y;
    #pragma unroll
    for (int px = 0; px < 4; px++){
        int gx = x0b + X0 + px;
        float* o = out + (size_t)(gy*L + gx)*128 + ocg*16;
        float4 o0 = make_float4(lrelu(acc[px][0]), lrelu(acc[px][1]), lrelu(acc[px][2]), lrelu(acc[px][3]));
        float4 o1 = make_float4(lrelu(acc[px][4]), lrelu(acc[px][5]), lrelu(acc[px][6]), lrelu(acc[px][7]));
        float4 o2 = make_float4(lrelu(acc[px][8]), lrelu(acc[px][9]), lrelu(acc[px][10]), lrelu(acc[px][11]));
        float4 o3 = make_float4(lrelu(acc[px][12]), lrelu(acc[px][13]), lrelu(acc[px][14]), lrelu(acc[px][15]));
        *(float4*)(o)      = o0;
        *(float4*)(o + 4)  = o1;
        *(float4*)(o + 8)  = o2;
        *(float4*)(o + 12) = o3;
    }
}

// ------------------------------------------------------------------
extern "C" void kernel_launch(void* const* d_in, const int* in_sizes, int n_in,
                              void* d_out, int out_size){
    (void)in_sizes; (void)n_in; (void)out_size;
    const float* x        = (const float*)d_in[0];
    const float* z        = (const float*)d_in[1];
    const float* plddt    = (const float*)d_in[2];
    const float* Wq       = (const float*)d_in[3];
    const float* Wk       = (const float*)d_in[4];
    const float* Wv       = (const float*)d_in[5];
    const float* Wp2a     = (const float*)d_in[6];
    const float* conv_a_w = (const float*)d_in[7];
    const float* conv_a_b = (const float*)d_in[8];
    const float* conv_m_w = (const float*)d_in[9];
    const float* conv_m_b = (const float*)d_in[10];
    const float* ln1_w    = (const float*)d_in[11];
    const float* ln1_b    = (const float*)d_in[12];
    const float* lin1_w   = (const float*)d_in[13];
    const float* lin1_b   = (const float*)d_in[14];
    const float* ln2_w    = (const float*)d_in[15];
    const float* ln2_b    = (const float*)d_in[16];
    const float* lin2_w   = (const float*)d_in[17];
    const float* lin2_b   = (const float*)d_in[18];
    const float* lnf_w    = (const float*)d_in[19];
    const float* lnf_b    = (const float*)d_in[20];
    const float* conv_p_w = (const float*)d_in[21];
    const float* conv_p_b = (const float*)d_in[22];
    float* out = (float*)d_out;

    float* S = nullptr;
    cudaGetSymbolAddress((void**)&S, g_scratch);
    float* q       = S + OFF_Q;
    float* k       = S + OFF_K;
    float* v       = S + OFF_V;
    float* a2h     = S + OFF_A2H;
    float* a8      = S + OFF_A8;
    float* afin    = S + OFF_AFIN;
    float* cat     = S + OFF_CAT;
    float* catn    = S + OFF_CATN;
    float* h1      = S + OFF_H1;
    float* h2      = S + OFF_H2;
    float* h3      = S + OFF_H3;
    float* wt      = S + OFF_WT;
    float* mean16  = S + OFF_MEAN16;
    float* rstd16  = S + OFF_RSTD16;
    float* mean9   = S + OFF_MEAN9;
    float* rstd9   = S + OFF_RSTD9;
    float* mean136 = S + OFF_MEAN136;
    float* rstd136 = S + OFF_RSTD136;
    float* psum    = S + OFF_PSUM;
    float* psq     = S + OFF_PSQ;

    // z per-channel stats (channels 0..127 of zp) — independent, start early
    zstats1_kernel<<<384, 256>>>(z, psum, psq);
    zstats2_kernel<<<128, 128>>>(psum, psq, mean136, rstd136);
    // conv_p weight transpose — independent
    wprep_kernel<<<612, 256>>>(conv_p_w, wt);

    // qkv + attention logits
    qkv_kernel<<<384, 256>>>(x, Wq, Wk, Wv, q, k, v);
    apair_kernel<<<dim3(48, 384), 256>>>(z, Wp2a, a2h);
    anode_kernel<<<dim3(12, 12, 8), dim3(32, 32)>>>(q, k, a2h);

    // conv_a path
    stats_kernel<<<16, 256>>>(a2h, 16, nullptr, mean16, rstd16);
    conva_kernel<<<dim3(24, 24), 256>>>(a2h, conv_a_w, conv_a_b, mean16, rstd16, a8);

    // conv_m path
    stats_kernel<<<9, 256>>>(a8, 8, plddt, mean9, rstd9);
    convm_kernel<<<dim3(24, 24), 256>>>(a8, plddt, conv_m_w, conv_m_b, mean9, rstd9, afin);

    // stats for afin channels (128..135 of zp)
    stats_kernel<<<8, 256>>>(afin, 8, nullptr, mean136 + 128, rstd136 + 128);

    // aggregations
    nfn_kernel<<<dim3(8, 12), dim3(32, 32)>>>(afin, v, cat);
    nfp_kernel<<<384, 256>>>(afin, z, cat);

    // MLP + final node LN
    ln_kernel<<<384, 256, 1280*sizeof(float)>>>(cat, nullptr, catn, ln1_w, ln1_b, 1280, 0);
    gemm_kernel<<<dim3(16, 12), dim3(16, 16)>>>(catn, lin1_w, lin1_b, h1, 384, 512, 1280);
    ln_kernel<<<384, 256, 512*sizeof(float)>>>(h1, nullptr, h2, ln2_w, ln2_b, 512, 1);
    gemm_kernel<<<dim3(8, 12), dim3(16, 16)>>>(h2, lin2_w, lin2_b, h3, 384, 256, 512);
    ln_kernel<<<384, 256, 256*sizeof(float)>>>(h3, x, out, lnf_w, lnf_b, 256, 0);

    // pair update
    convp_kernel<<<dim3(12, 12, 8), 256>>>(z, afin, wt, conv_p_b, mean136, rstd136,
                                           out + 384*256);
}